// round 5
// baseline (speedup 1.0000x reference)
#include <cuda_runtime.h>
#include <cstdint>

// Problem constants
#define Bc   4
#define Cc   256
#define Hc   64
#define Wc   64
#define OCc  256
#define Kc   9
#define Pc   4096
#define CKc  (Cc*Kc)    // 2304

// tf32-rounded, K-reordered weights: g_wtf[oc][k*256 + c]
__device__ float g_wtf[(size_t)OCc * CKc];

__device__ __forceinline__ uint32_t cvt_tf32(float f) {
    uint32_t r;
    asm("cvt.rna.tf32.f32 %0, %1;" : "=r"(r) : "f"(f));
    return r;
}

// ---------------------------------------------------------------------------
// Stage 0: round weights to tf32 AND reorder K: [oc][c*9+k] -> [oc][k*256+c]
// ---------------------------------------------------------------------------
__global__ __launch_bounds__(256) void round_weights(const float* __restrict__ w) {
    int i = blockIdx.x * 256 + threadIdx.x;    // dst index
    if (i < OCc * CKc) {
        int oc = i / CKc;
        int r  = i - oc * CKc;        // r = k*256 + c
        int k  = r >> 8;
        int c  = r & 255;
        g_wtf[i] = __uint_as_float(cvt_tf32(w[(size_t)oc * CKc + c * 9 + k]));
    }
}

// ---------------------------------------------------------------------------
// Fused deformable-im2col + tf32 mma.sync GEMM.
// out[b] = W[256 x 2304] * cols[b][2304 x 4096], cols produced on the fly.
// BM=256, BN=128, BK=16; K ordered k*256+c so each tile is 1 tap x 16 chans.
// ---------------------------------------------------------------------------
#define BM 256
#define BN 128
#define BK 16
#define NT (CKc / BK)      // 144 (16 tiles per tap, 9 taps)
#define ASTRB 80           // A smem row stride BYTES (ldmatrix conflict-free)
#define ABYTES (BM * ASTRB)          // 20480
#define BSTR 136           // B smem row stride (words)
#define BBYTES (BK * BSTR * 4)       // 8704
#define META_N (Kc * BN)             // 1152 entries
#define OFF_B   (3 * ABYTES)                         // 61440
#define OFF_MW  (OFF_B + 3 * BBYTES)                 // 87552
#define OFF_MI  (OFF_MW + META_N * 16)               // 105984
#define SM_TOTAL (OFF_MI + META_N * 16)              // 124416

__device__ __forceinline__ uint32_t smem_u32(const void* p) {
    uint32_t a;
    asm("{ .reg .u64 t; cvta.to.shared.u64 t, %1; cvt.u32.u64 %0, t; }"
        : "=r"(a) : "l"(p));
    return a;
}
__device__ __forceinline__ void cp_async16(uint32_t dst, const void* src) {
    asm volatile("cp.async.cg.shared.global [%0], [%1], 16;"
                 :: "r"(dst), "l"(src) : "memory");
}
__device__ __forceinline__ void cp_commit() {
    asm volatile("cp.async.commit_group;" ::: "memory");
}
template <int N>
__device__ __forceinline__ void cp_wait() {
    asm volatile("cp.async.wait_group %0;" :: "n"(N) : "memory");
}
__device__ __forceinline__ void ldmx4(uint32_t addr, uint32_t r[4]) {
    asm volatile("ldmatrix.sync.aligned.m8n8.x4.shared.b16 {%0,%1,%2,%3}, [%4];"
                 : "=r"(r[0]), "=r"(r[1]), "=r"(r[2]), "=r"(r[3]) : "r"(addr));
}
__device__ __forceinline__ void mma_tf32(float c[4],
                                         uint32_t a0, uint32_t a1, uint32_t a2, uint32_t a3,
                                         uint32_t b0, uint32_t b1) {
    asm volatile(
        "mma.sync.aligned.m16n8k8.row.col.f32.tf32.tf32.f32 "
        "{%0,%1,%2,%3}, {%4,%5,%6,%7}, {%8,%9}, {%0,%1,%2,%3};"
        : "+f"(c[0]), "+f"(c[1]), "+f"(c[2]), "+f"(c[3])
        : "r"(a0), "r"(a1), "r"(a2), "r"(a3), "r"(b0), "r"(b1));
}

__global__ __launch_bounds__(256, 1) void dcn_fused(
    const float* __restrict__ x,        // [B,C,H,W]
    const float* __restrict__ offset,   // [B,18,H,W]
    float* __restrict__ out)            // [B,OC,P]
{
    extern __shared__ char smraw[];
    float* sm = (float*)smraw;
    const uint32_t sbA = smem_u32(sm);
    float*  Bs    = sm + OFF_B / 4;                    // 3 x [BK][BSTR]
    float4* metaW = (float4*)(smraw + OFF_MW);         // [1152]
    int4*   metaI = (int4*)(smraw + OFF_MI);           // [1152]

    const int tid = threadIdx.x;
    const int wid = tid >> 5;
    const int lane = tid & 31;
    const int warp_m = wid >> 1;
    const int warp_n = wid & 1;
    const int r = lane >> 2;
    const int c4 = lane & 3;

    const int bx = blockIdx.x;      // N tile (0..31)
    const int b  = blockIdx.y;
    const int p0 = bx * BN;

    // gather role: cloc = channel-within-tile, p8 = 8-position group
    const int cloc = tid >> 4;      // 0..15
    const int p8   = tid & 15;      // 0..15

    // ---- metadata: 1152 (tap, p) entries ----
    for (int e = tid; e < META_N; e += 256) {
        int k = e >> 7;             // tap 0..8
        int pl = e & 127;
        int pg = p0 + pl;
        int ho = pg >> 6, wo = pg & 63;
        int ki = k / 3, kj = k - 3 * ki;

        const float* offb = offset + ((size_t)b * 18) * Pc;
        float dy = offb[(2 * k    ) * Pc + pg];
        float dx = offb[(2 * k + 1) * Pc + pg];

        float ph = (float)(ho - 1 + ki) + dy;
        float pw = (float)(wo - 1 + kj) + dx;
        float h0f = floorf(ph), w0f = floorf(pw);
        float lh = ph - h0f,    lw = pw - w0f;
        int h0 = (int)h0f, w0 = (int)w0f;
        int h1 = h0 + 1,   w1 = w0 + 1;

        float vh0 = (h0 >= 0 && h0 < Hc) ? 1.f : 0.f;
        float vh1 = (h1 >= 0 && h1 < Hc) ? 1.f : 0.f;
        float vw0 = (w0 >= 0 && w0 < Wc) ? 1.f : 0.f;
        float vw1 = (w1 >= 0 && w1 < Wc) ? 1.f : 0.f;

        float4 wv;
        wv.x = (1.f - lh) * (1.f - lw) * vh0 * vw0;
        wv.y = (1.f - lh) * lw         * vh0 * vw1;
        wv.z = lh * (1.f - lw)         * vh1 * vw0;
        wv.w = lh * lw                 * vh1 * vw1;

        int ih0 = min(max(h0, 0), Hc - 1);
        int ih1 = min(max(h1, 0), Hc - 1);
        int iw0 = min(max(w0, 0), Wc - 1);
        int iw1 = min(max(w1, 0), Wc - 1);
        int4 iv;
        iv.x = ih0 * Wc + iw0;
        iv.y = ih0 * Wc + iw1;
        iv.z = ih1 * Wc + iw0;
        iv.w = ih1 * Wc + iw1;

        metaW[e] = wv;
        metaI[e] = iv;
    }
    __syncthreads();

    float acc[4][8][4];
#pragma unroll
    for (int i = 0; i < 4; ++i)
#pragma unroll
        for (int j = 0; j < 8; ++j)
#pragma unroll
            for (int q = 0; q < 4; ++q) acc[i][j][q] = 0.f;

    // A staging via cp.async: 4 chunks/thread
    auto issue_A = [&](int t) {
        const uint32_t abase = sbA + (t % 3) * ABYTES;
#pragma unroll
        for (int i = 0; i < 4; ++i) {
            int ch = tid + i * 256;
            int m = ch >> 2, k4 = ch & 3;
            cp_async16(abase + (uint32_t)(m * ASTRB + k4 * 16),
                       g_wtf + (size_t)m * CKc + t * BK + k4 * 4);
        }
    };

    // gather for tile t: tap = t>>4, channels (t&15)*16 + cloc, 8 p-values
    auto gather_issue = [&](int t, float g[32]) {
        int k = t >> 4;
        int c = ((t & 15) << 4) + cloc;
        const float* xrow = x + (((size_t)b * Cc + c) << 12);
        int ebase = (k << 7) + p8 * 8;
#pragma unroll
        for (int j = 0; j < 8; ++j) {
            int4 id = metaI[ebase + j];
            g[j * 4 + 0] = __ldg(xrow + id.x);
            g[j * 4 + 1] = __ldg(xrow + id.y);
            g[j * 4 + 2] = __ldg(xrow + id.z);
            g[j * 4 + 3] = __ldg(xrow + id.w);
        }
    };
    auto gather_combine_sts = [&](int t, float g[32]) {
        int k = t >> 4;
        int ebase = (k << 7) + p8 * 8;
        uint32_t v[8];
#pragma unroll
        for (int j = 0; j < 8; ++j) {
            float4 wv = metaW[ebase + j];
            float val = g[j * 4 + 0] * wv.x + g[j * 4 + 1] * wv.y
                      + g[j * 4 + 2] * wv.z + g[j * 4 + 3] * wv.w;
            v[j] = cvt_tf32(val);
        }
        uint4* dst = (uint4*)(Bs + (t % 3) * (BBYTES / 4) + cloc * BSTR + p8 * 8);
        dst[0] = make_uint4(v[0], v[1], v[2], v[3]);
        dst[1] = make_uint4(v[4], v[5], v[6], v[7]);
    };

    // ---- prologue ----
    issue_A(0); cp_commit();
    issue_A(1); cp_commit();
    {
        float g[32];
        gather_issue(0, g);
        gather_combine_sts(0, g);
    }
    __syncthreads();   // B tile 0 visible

    const uint32_t a_lane = (uint32_t)((warp_m * 64 + (lane & 15)) * ASTRB
                                       + ((lane & 16) ? 16 : 0));

    for (int t = 0; t < NT; ++t) {
        cp_wait<1>();          // A(t) landed
        __syncthreads();       // + B(t) STS visible, prev buffers released

        if (t + 2 < NT) issue_A(t + 2);
        cp_commit();

        float g[32];
        if (t + 1 < NT) gather_issue(t + 1, g);

        const uint32_t abase = sbA + (t % 3) * ABYTES + a_lane;
        const float* Bp = Bs + (t % 3) * (BBYTES / 4) + warp_n * 64;

        // ---- kk = 0..7 ----
        {
            uint32_t af[4][4];
#pragma unroll
            for (int mi = 0; mi < 4; ++mi)
                ldmx4(abase + (uint32_t)(mi * 16 * ASTRB), af[mi]);
            uint32_t bf[8][2];
#pragma unroll
            for (int ni = 0; ni < 8; ++ni) {
                int n = ni * 8 + r;
                bf[ni][0] = __float_as_uint(Bp[(c4    ) * BSTR + n]);
                bf[ni][1] = __float_as_uint(Bp[(c4 + 4) * BSTR + n]);
            }
#pragma unroll
            for (int mi = 0; mi < 4; ++mi)
#pragma unroll
                for (int ni = 0; ni < 8; ++ni)
                    mma_tf32(acc[mi][ni], af[mi][0], af[mi][1], af[mi][2], af[mi][3],
                             bf[ni][0], bf[ni][1]);
        }

        // combine gathers mid-tile (LDG latency covered by the mma block above)
        if (t + 1 < NT) gather_combine_sts(t + 1, g);

        // ---- kk = 8..15 ----
        {
            uint32_t af[4][4];
#pragma unroll
            for (int mi = 0; mi < 4; ++mi)
                ldmx4(abase + (uint32_t)(mi * 16 * ASTRB + 32), af[mi]);
            uint32_t bf[8][2];
#pragma unroll
            for (int ni = 0; ni < 8; ++ni) {
                int n = ni * 8 + r;
                bf[ni][0] = __float_as_uint(Bp[(8 + c4    ) * BSTR + n]);
                bf[ni][1] = __float_as_uint(Bp[(8 + c4 + 4) * BSTR + n]);
            }
#pragma unroll
            for (int mi = 0; mi < 4; ++mi)
#pragma unroll
                for (int ni = 0; ni < 8; ++ni)
                    mma_tf32(acc[mi][ni], af[mi][0], af[mi][1], af[mi][2], af[mi][3],
                             bf[ni][0], bf[ni][1]);
        }
    }

    // ---- epilogue ----
    float* outb = out + (size_t)b * OCc * Pc + (size_t)p0;
#pragma unroll
    for (int mi = 0; mi < 4; ++mi) {
        int oc0 = warp_m * 64 + mi * 16 + r;
#pragma unroll
        for (int ni = 0; ni < 8; ++ni) {
            int p = warp_n * 64 + ni * 8 + 2 * c4;
            float2 v0 = make_float2(acc[mi][ni][0], acc[mi][ni][1]);
            float2 v1 = make_float2(acc[mi][ni][2], acc[mi][ni][3]);
            *(float2*)(outb + (size_t) oc0      * Pc + p) = v0;
            *(float2*)(outb + (size_t)(oc0 + 8) * Pc + p) = v1;
        }
    }
}

// ---------------------------------------------------------------------------
extern "C" void kernel_launch(void* const* d_in, const int* in_sizes, int n_in,
                              void* d_out, int out_size) {
    const float* x      = (const float*)d_in[0];
    const float* offset = (const float*)d_in[1];
    const float* weight = (const float*)d_in[2];
    float* out = (float*)d_out;

    cudaFuncSetAttribute(dcn_fused,
                         cudaFuncAttributeMaxDynamicSharedMemorySize, SM_TOTAL);

    round_weights<<<(OCc * CKc + 255) / 256, 256>>>(weight);

    dim3 grid(Pc / BN, Bc);   // (32, 4) = 128 CTAs
    dcn_fused<<<grid, 256, SM_TOTAL>>>(x, offset, out);
}

// round 6
// speedup vs baseline: 2.4490x; 2.4490x over previous
#include <cuda_runtime.h>
#include <cstdint>

// Problem constants
#define Bc   4
#define Cc   256
#define Hc   64
#define Wc   64
#define OCc  256
#define Kc   9
#define Pc   4096
#define CKc  (Cc*Kc)    // 2304

__device__ float g_cols[(size_t)Bc * CKc * Pc];
__device__ float g_wtf[(size_t)OCc * CKc];      // tf32-rounded weights

__device__ __forceinline__ uint32_t cvt_tf32(float f) {
    uint32_t r;
    asm("cvt.rna.tf32.f32 %0, %1;" : "=r"(r) : "f"(f));
    return r;
}

// ---------------------------------------------------------------------------
// Stage 0: round weights to tf32
// ---------------------------------------------------------------------------
__global__ __launch_bounds__(256) void round_weights(const float* __restrict__ w) {
    int i = blockIdx.x * 256 + threadIdx.x;
    if (i < OCc * CKc) g_wtf[i] = __uint_as_float(cvt_tf32(w[i]));
}

// ---------------------------------------------------------------------------
// Stage 1: deformable im2col — stores tf32-rounded values (R4-proven).
// ---------------------------------------------------------------------------
__global__ __launch_bounds__(256) void dcn_im2col(
    const float* __restrict__ x,
    const float* __restrict__ offset)
{
    int tid = blockIdx.x * 256 + threadIdx.x;
    int p = tid & (Pc - 1);
    int k = (tid >> 12) % Kc;
    int b = tid / (Pc * Kc);

    int ho = p >> 6;
    int wo = p & 63;
    int ki = k / 3;
    int kj = k - 3 * ki;

    const float* offb = offset + ((size_t)b * 18) * Pc;
    float dy = offb[(2 * k    ) * Pc + p];
    float dx = offb[(2 * k + 1) * Pc + p];

    float ph = (float)(ho - 1 + ki) + dy;
    float pw = (float)(wo - 1 + kj) + dx;

    float h0f = floorf(ph), w0f = floorf(pw);
    float lh = ph - h0f,    lw = pw - w0f;
    int h0 = (int)h0f, w0 = (int)w0f;
    int h1 = h0 + 1,   w1 = w0 + 1;

    float vh0 = (h0 >= 0 && h0 < Hc) ? 1.f : 0.f;
    float vh1 = (h1 >= 0 && h1 < Hc) ? 1.f : 0.f;
    float vw0 = (w0 >= 0 && w0 < Wc) ? 1.f : 0.f;
    float vw1 = (w1 >= 0 && w1 < Wc) ? 1.f : 0.f;

    float w00 = (1.f - lh) * (1.f - lw) * vh0 * vw0;
    float w01 = (1.f - lh) * lw         * vh0 * vw1;
    float w10 = lh * (1.f - lw)         * vh1 * vw0;
    float w11 = lh * lw                 * vh1 * vw1;

    int ih0 = min(max(h0, 0), Hc - 1);
    int ih1 = min(max(h1, 0), Hc - 1);
    int iw0 = min(max(w0, 0), Wc - 1);
    int iw1 = min(max(w1, 0), Wc - 1);

    int i00 = ih0 * Wc + iw0;
    int i01 = ih0 * Wc + iw1;
    int i10 = ih1 * Wc + iw0;
    int i11 = ih1 * Wc + iw1;

    const float* xb = x + (size_t)b * Cc * Pc;
    float* colp = g_cols + (size_t)b * CKc * Pc + (size_t)k * Pc + p;

#pragma unroll 4
    for (int c = 0; c < Cc; ++c) {
        const float* xc = xb + (size_t)c * Pc;
        float v = w00 * xc[i00] + w01 * xc[i01] + w10 * xc[i10] + w11 * xc[i11];
        colp[(size_t)c * (Kc * Pc)] = __uint_as_float(cvt_tf32(v));
    }
}

// ---------------------------------------------------------------------------
// Stage 2: tf32 mma.sync GEMM, 512 threads, warp tile 64x32 (4x4 warp grid).
// BM=256, BN=128, BK=16, 4-stage cp.async pipeline, ldmatrix A.
// ---------------------------------------------------------------------------
#define BM 256
#define BN 128
#define BK 16
#define NT (CKc / BK)      // 144
#define STAGES 4
#define ASTRB 80           // A smem row stride BYTES
#define ABYTES (BM * ASTRB)          // 20480
#define BSTR 136           // B smem row stride (words); 136 % 32 == 8 -> conflict-free
#define BBYTES (BK * BSTR * 4)       // 8704
#define SM_TOTAL (STAGES * (ABYTES + BBYTES))   // 116736

__device__ __forceinline__ uint32_t smem_u32(const void* p) {
    uint32_t a;
    asm("{ .reg .u64 t; cvta.to.shared.u64 t, %1; cvt.u32.u64 %0, t; }"
        : "=r"(a) : "l"(p));
    return a;
}
__device__ __forceinline__ void cp_async16(uint32_t dst, const void* src) {
    asm volatile("cp.async.cg.shared.global [%0], [%1], 16;"
                 :: "r"(dst), "l"(src) : "memory");
}
__device__ __forceinline__ void cp_commit() {
    asm volatile("cp.async.commit_group;" ::: "memory");
}
template <int N>
__device__ __forceinline__ void cp_wait() {
    asm volatile("cp.async.wait_group %0;" :: "n"(N) : "memory");
}
__device__ __forceinline__ void ldmx4(uint32_t addr, uint32_t r[4]) {
    asm volatile("ldmatrix.sync.aligned.m8n8.x4.shared.b16 {%0,%1,%2,%3}, [%4];"
                 : "=r"(r[0]), "=r"(r[1]), "=r"(r[2]), "=r"(r[3]) : "r"(addr));
}
__device__ __forceinline__ void mma_tf32(float c[4],
                                         uint32_t a0, uint32_t a1, uint32_t a2, uint32_t a3,
                                         uint32_t b0, uint32_t b1) {
    asm volatile(
        "mma.sync.aligned.m16n8k8.row.col.f32.tf32.tf32.f32 "
        "{%0,%1,%2,%3}, {%4,%5,%6,%7}, {%8,%9}, {%0,%1,%2,%3};"
        : "+f"(c[0]), "+f"(c[1]), "+f"(c[2]), "+f"(c[3])
        : "r"(a0), "r"(a1), "r"(a2), "r"(a3), "r"(b0), "r"(b1));
}

__global__ __launch_bounds__(512, 1) void dcn_gemm_mma(
    float* __restrict__ out)            // [B, OC, P]
{
    extern __shared__ float sm[];
    const uint32_t sbA = smem_u32(sm);                       // STAGES x ABYTES
    const uint32_t sbB = sbA + STAGES * ABYTES;
    float* Bs = sm + (STAGES * ABYTES) / 4;

    const int tid = threadIdx.x;
    const int wid = tid >> 5;          // 0..15
    const int lane = tid & 31;
    const int warp_m = wid >> 2;       // 0..3  -> M offset *64
    const int warp_n = wid & 3;        // 0..3  -> N offset *32
    const int r = lane >> 2;
    const int c4 = lane & 3;

    const int bx = blockIdx.x;         // N tile (0..31)
    const int b  = blockIdx.y;         // batch

    const float* Bg = g_cols + (size_t)b * CKc * Pc + (size_t)bx * BN;

    float acc[4][4][4];
#pragma unroll
    for (int i = 0; i < 4; ++i)
#pragma unroll
        for (int j = 0; j < 4; ++j)
#pragma unroll
            for (int q = 0; q < 4; ++q) acc[i][j][q] = 0.f;

    // Staging: A = 1024 float4 chunks (2/thread), B = 512 chunks (1/thread)
    auto issue_tile = [&](int t) {
        const int buf = t % STAGES;
        const uint32_t abase = sbA + buf * ABYTES;
        const uint32_t bbase = sbB + buf * BBYTES;
#pragma unroll
        for (int i = 0; i < 2; ++i) {
            int ch = tid + i * 512;
            int m = ch >> 2, k4 = ch & 3;
            cp_async16(abase + (uint32_t)(m * ASTRB + k4 * 16),
                       g_wtf + (size_t)m * CKc + t * BK + k4 * 4);
        }
        {
            int k = tid >> 5, n16 = tid & 31;
            cp_async16(bbase + (uint32_t)(k * (BSTR * 4) + n16 * 16),
                       Bg + (size_t)(t * BK + k) * Pc + n16 * 4);
        }
    };

    // ---- prologue: stages 0..2 ----
#pragma unroll
    for (int s = 0; s < STAGES - 1; ++s) { issue_tile(s); cp_commit(); }

    const uint32_t a_lane = (uint32_t)((warp_m * 64 + (lane & 15)) * ASTRB
                                       + ((lane & 16) ? 16 : 0));

    for (int t = 0; t < NT; ++t) {
        const int buf = t % STAGES;
        cp_wait<STAGES - 2>();
        __syncthreads();

        if (t + STAGES - 1 < NT) issue_tile(t + STAGES - 1);
        cp_commit();   // always commit -> wait_group counting stays exact

        const uint32_t abase = sbA + buf * ABYTES + a_lane;
        const float* Bp = Bs + buf * (BBYTES / 4) + warp_n * 32;

#pragma unroll
        for (int kk8 = 0; kk8 < 2; ++kk8) {
            uint32_t af[4][4];
#pragma unroll
            for (int mi = 0; mi < 4; ++mi)
                ldmx4(abase + (uint32_t)(mi * 16 * ASTRB + kk8 * 32), af[mi]);

            const int kk = kk8 * 8;
            uint32_t bf[4][2];
#pragma unroll
            for (int ni = 0; ni < 4; ++ni) {
                int n = ni * 8 + r;
                bf[ni][0] = __float_as_uint(Bp[(kk + c4    ) * BSTR + n]);
                bf[ni][1] = __float_as_uint(Bp[(kk + c4 + 4) * BSTR + n]);
            }
#pragma unroll
            for (int mi = 0; mi < 4; ++mi)
#pragma unroll
                for (int ni = 0; ni < 4; ++ni)
                    mma_tf32(acc[mi][ni], af[mi][0], af[mi][1], af[mi][2], af[mi][3],
                             bf[ni][0], bf[ni][1]);
        }
    }

    // ---- epilogue: direct STG from fragments ----
    float* outb = out + (size_t)b * OCc * Pc + (size_t)bx * BN;
#pragma unroll
    for (int mi = 0; mi < 4; ++mi) {
        int oc0 = warp_m * 64 + mi * 16 + r;
#pragma unroll
        for (int ni = 0; ni < 4; ++ni) {
            int p = warp_n * 32 + ni * 8 + 2 * c4;
            float2 v0 = make_float2(acc[mi][ni][0], acc[mi][ni][1]);
            float2 v1 = make_float2(acc[mi][ni][2], acc[mi][ni][3]);
            *(float2*)(outb + (size_t) oc0      * Pc + p) = v0;
            *(float2*)(outb + (size_t)(oc0 + 8) * Pc + p) = v1;
        }
    }
}

// ---------------------------------------------------------------------------
extern "C" void kernel_launch(void* const* d_in, const int* in_sizes, int n_in,
                              void* d_out, int out_size) {
    const float* x      = (const float*)d_in[0];
    const float* offset = (const float*)d_in[1];
    const float* weight = (const float*)d_in[2];
    float* out = (float*)d_out;

    cudaFuncSetAttribute(dcn_gemm_mma,
                         cudaFuncAttributeMaxDynamicSharedMemorySize, SM_TOTAL);

    round_weights<<<(OCc * CKc + 255) / 256, 256>>>(weight);
    dcn_im2col<<<(Bc * Kc * Pc) / 256, 256>>>(x, offset);

    dim3 grid(Pc / BN, Bc);   // (32, 4) = 128 CTAs
    dcn_gemm_mma<<<grid, 512, SM_TOTAL>>>(out);
}

// round 7
// speedup vs baseline: 2.6098x; 1.0657x over previous
#include <cuda_runtime.h>
#include <cstdint>

// Problem constants
#define Bc   4
#define Cc   256
#define Hc   64
#define Wc   64
#define OCc  256
#define Kc   9
#define Pc   4096
#define CKc  (Cc*Kc)    // 2304

__device__ float g_cols[(size_t)Bc * CKc * Pc];
__device__ float g_wtf[(size_t)OCc * CKc];      // tf32-rounded weights

__device__ __forceinline__ uint32_t cvt_tf32(float f) {
    uint32_t r;
    asm("cvt.rna.tf32.f32 %0, %1;" : "=r"(r) : "f"(f));
    return r;
}

// ---------------------------------------------------------------------------
// Stage 0: round weights to tf32
// ---------------------------------------------------------------------------
__global__ __launch_bounds__(256) void round_weights(const float* __restrict__ w) {
    int i = blockIdx.x * 256 + threadIdx.x;
    if (i < OCc * CKc) g_wtf[i] = __uint_as_float(cvt_tf32(w[i]));
}

// ---------------------------------------------------------------------------
// Stage 1: deformable im2col — stores tf32-rounded values.
// ---------------------------------------------------------------------------
__global__ __launch_bounds__(256) void dcn_im2col(
    const float* __restrict__ x,
    const float* __restrict__ offset)
{
    int tid = blockIdx.x * 256 + threadIdx.x;
    int p = tid & (Pc - 1);
    int k = (tid >> 12) % Kc;
    int b = tid / (Pc * Kc);

    int ho = p >> 6;
    int wo = p & 63;
    int ki = k / 3;
    int kj = k - 3 * ki;

    const float* offb = offset + ((size_t)b * 18) * Pc;
    float dy = offb[(2 * k    ) * Pc + p];
    float dx = offb[(2 * k + 1) * Pc + p];

    float ph = (float)(ho - 1 + ki) + dy;
    float pw = (float)(wo - 1 + kj) + dx;

    float h0f = floorf(ph), w0f = floorf(pw);
    float lh = ph - h0f,    lw = pw - w0f;
    int h0 = (int)h0f, w0 = (int)w0f;
    int h1 = h0 + 1,   w1 = w0 + 1;

    float vh0 = (h0 >= 0 && h0 < Hc) ? 1.f : 0.f;
    float vh1 = (h1 >= 0 && h1 < Hc) ? 1.f : 0.f;
    float vw0 = (w0 >= 0 && w0 < Wc) ? 1.f : 0.f;
    float vw1 = (w1 >= 0 && w1 < Wc) ? 1.f : 0.f;

    float w00 = (1.f - lh) * (1.f - lw) * vh0 * vw0;
    float w01 = (1.f - lh) * lw         * vh0 * vw1;
    float w10 = lh * (1.f - lw)         * vh1 * vw0;
    float w11 = lh * lw                 * vh1 * vw1;

    int ih0 = min(max(h0, 0), Hc - 1);
    int ih1 = min(max(h1, 0), Hc - 1);
    int iw0 = min(max(w0, 0), Wc - 1);
    int iw1 = min(max(w1, 0), Wc - 1);

    int i00 = ih0 * Wc + iw0;
    int i01 = ih0 * Wc + iw1;
    int i10 = ih1 * Wc + iw0;
    int i11 = ih1 * Wc + iw1;

    const float* xb = x + (size_t)b * Cc * Pc;
    float* colp = g_cols + (size_t)b * CKc * Pc + (size_t)k * Pc + p;

#pragma unroll 4
    for (int c = 0; c < Cc; ++c) {
        const float* xc = xb + (size_t)c * Pc;
        float v = w00 * xc[i00] + w01 * xc[i01] + w10 * xc[i10] + w11 * xc[i11];
        colp[(size_t)c * (Kc * Pc)] = __uint_as_float(cvt_tf32(v));
    }
}

// ---------------------------------------------------------------------------
// Stage 2: tf32 mma.sync GEMM. BM=128, BN=128, BK=16, 3 stages, 256 threads,
// 2 CTAs/SM.  Warp grid 2(m) x 4(n), warp tile 64x32.
// ---------------------------------------------------------------------------
#define BM 128
#define BN 128
#define BK 16
#define NT (CKc / BK)      // 144
#define STAGES 3
#define ASTRB 80           // A smem row stride BYTES
#define ABYTES (BM * ASTRB)          // 10240
#define BSTR 136           // B smem row stride (words)
#define BBYTES (BK * BSTR * 4)       // 8704
#define SM_TOTAL (STAGES * (ABYTES + BBYTES))   // 56832

__device__ __forceinline__ uint32_t smem_u32(const void* p) {
    uint32_t a;
    asm("{ .reg .u64 t; cvta.to.shared.u64 t, %1; cvt.u32.u64 %0, t; }"
        : "=r"(a) : "l"(p));
    return a;
}
__device__ __forceinline__ void cp_async16(uint32_t dst, const void* src) {
    asm volatile("cp.async.cg.shared.global [%0], [%1], 16;"
                 :: "r"(dst), "l"(src) : "memory");
}
__device__ __forceinline__ void cp_commit() {
    asm volatile("cp.async.commit_group;" ::: "memory");
}
template <int N>
__device__ __forceinline__ void cp_wait() {
    asm volatile("cp.async.wait_group %0;" :: "n"(N) : "memory");
}
__device__ __forceinline__ void ldmx4(uint32_t addr, uint32_t r[4]) {
    asm volatile("ldmatrix.sync.aligned.m8n8.x4.shared.b16 {%0,%1,%2,%3}, [%4];"
                 : "=r"(r[0]), "=r"(r[1]), "=r"(r[2]), "=r"(r[3]) : "r"(addr));
}
__device__ __forceinline__ void mma_tf32(float c[4],
                                         uint32_t a0, uint32_t a1, uint32_t a2, uint32_t a3,
                                         uint32_t b0, uint32_t b1) {
    asm volatile(
        "mma.sync.aligned.m16n8k8.row.col.f32.tf32.tf32.f32 "
        "{%0,%1,%2,%3}, {%4,%5,%6,%7}, {%8,%9}, {%0,%1,%2,%3};"
        : "+f"(c[0]), "+f"(c[1]), "+f"(c[2]), "+f"(c[3])
        : "r"(a0), "r"(a1), "r"(a2), "r"(a3), "r"(b0), "r"(b1));
}

__global__ __launch_bounds__(256, 2) void dcn_gemm_mma(
    float* __restrict__ out)            // [B, OC, P]
{
    extern __shared__ float sm[];
    const uint32_t sbA = smem_u32(sm);                  // STAGES x ABYTES
    const uint32_t sbB = sbA + STAGES * ABYTES;
    float* Bs = sm + (STAGES * ABYTES) / 4;

    const int tid = threadIdx.x;
    const int wid = tid >> 5;          // 0..7
    const int lane = tid & 31;
    const int warp_m = wid >> 2;       // 0..1  -> M offset *64
    const int warp_n = wid & 3;        // 0..3  -> N offset *32
    const int r = lane >> 2;
    const int c4 = lane & 3;

    const int bx = blockIdx.x;         // N tile (0..31)
    const int by = blockIdx.y;         // M tile (0..1)
    const int b  = blockIdx.z;         // batch

    const float* Ag = g_wtf + (size_t)by * BM * CKc;
    const float* Bg = g_cols + (size_t)b * CKc * Pc + (size_t)bx * BN;

    float acc[4][4][4];
#pragma unroll
    for (int i = 0; i < 4; ++i)
#pragma unroll
        for (int j = 0; j < 4; ++j)
#pragma unroll
            for (int q = 0; q < 4; ++q) acc[i][j][q] = 0.f;

    // Staging: A = 512 float4 chunks (2/thread), B = 512 chunks (2/thread)
    auto issue_tile = [&](int t) {
        const int buf = t % STAGES;
        const uint32_t abase = sbA + buf * ABYTES;
        const uint32_t bbase = sbB + buf * BBYTES;
#pragma unroll
        for (int i = 0; i < 2; ++i) {
            int ch = tid + i * 256;
            int m = ch >> 2, k4 = ch & 3;
            cp_async16(abase + (uint32_t)(m * ASTRB + k4 * 16),
                       Ag + (size_t)m * CKc + t * BK + k4 * 4);
        }
#pragma unroll
        for (int j = 0; j < 2; ++j) {
            int ch = tid + j * 256;
            int k = ch >> 5, n16 = ch & 31;
            cp_async16(bbase + (uint32_t)(k * (BSTR * 4) + n16 * 16),
                       Bg + (size_t)(t * BK + k) * Pc + n16 * 4);
        }
    };

    // ---- prologue: stages 0,1 ----
#pragma unroll
    for (int s = 0; s < STAGES - 1; ++s) { issue_tile(s); cp_commit(); }

    const uint32_t a_lane = (uint32_t)((warp_m * 64 + (lane & 15)) * ASTRB
                                       + ((lane & 16) ? 16 : 0));

    for (int t = 0; t < NT; ++t) {
        const int buf = t % STAGES;
        cp_wait<STAGES - 2>();
        __syncthreads();

        if (t + STAGES - 1 < NT) issue_tile(t + STAGES - 1);
        cp_commit();   // always commit -> wait_group counting stays exact

        const uint32_t abase = sbA + buf * ABYTES + a_lane;
        const float* Bp = Bs + buf * (BBYTES / 4) + warp_n * 32;

#pragma unroll
        for (int kk8 = 0; kk8 < 2; ++kk8) {
            uint32_t af[4][4];
#pragma unroll
            for (int mi = 0; mi < 4; ++mi)
                ldmx4(abase + (uint32_t)(mi * 16 * ASTRB + kk8 * 32), af[mi]);

            const int kk = kk8 * 8;
            uint32_t bf[4][2];
#pragma unroll
            for (int ni = 0; ni < 4; ++ni) {
                int n = ni * 8 + r;
                bf[ni][0] = __float_as_uint(Bp[(kk + c4    ) * BSTR + n]);
                bf[ni][1] = __float_as_uint(Bp[(kk + c4 + 4) * BSTR + n]);
            }
#pragma unroll
            for (int mi = 0; mi < 4; ++mi)
#pragma unroll
                for (int ni = 0; ni < 4; ++ni)
                    mma_tf32(acc[mi][ni], af[mi][0], af[mi][1], af[mi][2], af[mi][3],
                             bf[ni][0], bf[ni][1]);
        }
    }

    // ---- epilogue: direct STG from fragments ----
    float* outb = out + ((size_t)b * OCc + by * BM) * Pc + (size_t)bx * BN;
#pragma unroll
    for (int mi = 0; mi < 4; ++mi) {
        int oc0 = warp_m * 64 + mi * 16 + r;
#pragma unroll
        for (int ni = 0; ni < 4; ++ni) {
            int p = warp_n * 32 + ni * 8 + 2 * c4;
            float2 v0 = make_float2(acc[mi][ni][0], acc[mi][ni][1]);
            float2 v1 = make_float2(acc[mi][ni][2], acc[mi][ni][3]);
            *(float2*)(outb + (size_t) oc0      * Pc + p) = v0;
            *(float2*)(outb + (size_t)(oc0 + 8) * Pc + p) = v1;
        }
    }
}

// ---------------------------------------------------------------------------
extern "C" void kernel_launch(void* const* d_in, const int* in_sizes, int n_in,
                              void* d_out, int out_size) {
    const float* x      = (const float*)d_in[0];
    const float* offset = (const float*)d_in[1];
    const float* weight = (const float*)d_in[2];
    float* out = (float*)d_out;

    cudaFuncSetAttribute(dcn_gemm_mma,
                         cudaFuncAttributeMaxDynamicSharedMemorySize, SM_TOTAL);

    round_weights<<<(OCc * CKc + 255) / 256, 256>>>(weight);
    dcn_im2col<<<(Bc * Kc * Pc) / 256, 256>>>(x, offset);

    dim3 grid(Pc / BN, OCc / BM, Bc);   // (32, 2, 4) = 256 CTAs, 2 per SM
    dcn_gemm_mma<<<grid, 256, SM_TOTAL>>>(out);
}